// round 5
// baseline (speedup 1.0000x reference)
#include <cuda_runtime.h>
#include <stdint.h>

#define AN 196416
#define NC 80
#define KK 1000
#define CAP 2048
#define SPLIT 4
#define PARTS 11   // mask CTAs per class: 11*8 warps = 88, x6 tasks = 528

// ---------------- global scratch ----------------
__device__ float              g_scoresT[(size_t)NC * AN];
__device__ unsigned           g_hist[NC * 256];
__device__ int                g_cnt[NC];
__device__ unsigned long long g_cand[NC * CAP];
__device__ float4             g_box  [NC * 1024];
__device__ float              g_score[NC * 1024];
__device__ unsigned           g_vb   [NC * 32];
__device__ unsigned           g_maskT[NC * 32 * 1024];   // [class][wordcol][row]
__device__ unsigned           g_diag [NC * 1024];

__device__ __forceinline__ unsigned order_key(float x) {
    unsigned u = __float_as_uint(x);
    return (u & 0x80000000u) ? ~u : (u | 0x80000000u);
}

// ---------------------------------------------------------------------------
// K1: transpose [AN, NC] -> [NC, AN]; block (0,0) also zeroes hist/cnt
// ---------------------------------------------------------------------------
__global__ __launch_bounds__(512) void transpose_kernel(const float* __restrict__ cls) {
    __shared__ float tile[2][32][33];
    int tid = threadIdx.x;
    if (blockIdx.x == 0 && blockIdx.y == 0) {
        for (int i = tid; i < NC * 256; i += 512) g_hist[i] = 0;
        if (tid < NC) g_cnt[tid] = 0;
    }
    int c0 = blockIdx.y * 32;
    int a0 = blockIdx.x * 64;
    int t = tid >> 8;                 // which 32-anchor tile
    int r = (tid >> 3) & 31;          // anchor row in tile
    int q = tid & 7;                  // class quad
    int c = c0 + q * 4;
    float4 v = make_float4(0.f, 0.f, 0.f, 0.f);
    if (c < NC)
        v = *reinterpret_cast<const float4*>(&cls[(size_t)(a0 + t * 32 + r) * NC + c]);
    tile[t][r][q * 4 + 0] = v.x;
    tile[t][r][q * 4 + 1] = v.y;
    tile[t][r][q * 4 + 2] = v.z;
    tile[t][r][q * 4 + 3] = v.w;
    __syncthreads();
    int cc = (tid & 255) >> 3;        // class within tile
    int ct = c0 + cc;
    if (ct < NC) {
        float4 o;
        o.x = tile[t][q * 4 + 0][cc];
        o.y = tile[t][q * 4 + 1][cc];
        o.z = tile[t][q * 4 + 2][cc];
        o.w = tile[t][q * 4 + 3][cc];
        *reinterpret_cast<float4*>(&g_scoresT[(size_t)ct * AN + a0 + t * 32 + q * 4]) = o;
    }
}

// ---------------------------------------------------------------------------
// K2a: one-pass 256-bin per-thread u8 histogram, grid (SPLIT, NC)
// ---------------------------------------------------------------------------
__global__ __launch_bounds__(512, 1) void hist_kernel() {
    extern __shared__ unsigned char h8[];   // 256 bins x 512 byte-slots = 128KB
    const int c = blockIdx.y, part = blockIdx.x;
    const int tid = threadIdx.x, lane = tid & 31, wid = tid >> 5;
    unsigned* h32 = reinterpret_cast<unsigned*>(h8);
    for (int i = tid; i < 512 * 256 / 4; i += 512) h32[i] = 0;
    __syncthreads();

    const int n4 = AN / 4 / SPLIT;          // 12276
    const float4* row4 = reinterpret_cast<const float4*>(g_scoresT + (size_t)c * AN) + part * n4;
    const int slot = (tid & 127) * 4 + (tid >> 7);   // conflict-free byte slot
    for (int i = tid; i < n4; i += 512) {
        float4 v = row4[i];
#define HB(x) { int b = (int)((x) * 256.0f); b = b < 0 ? 0 : (b > 255 ? 255 : b); \
                h8[b * 512 + slot] += 1; }
        HB(v.x) HB(v.y) HB(v.z) HB(v.w)
#undef HB
    }
    __syncthreads();

    for (int b = wid; b < 256; b += 16) {
        const unsigned* p = reinterpret_cast<const unsigned*>(h8 + b * 512);
        unsigned s = 0;
#pragma unroll
        for (int k = 0; k < 4; ++k) s = __dp4a(p[k * 32 + lane], 0x01010101u, s);
#pragma unroll
        for (int o = 16; o; o >>= 1) s += __shfl_down_sync(0xFFFFFFFFu, s, o);
        if (lane == 0) atomicAdd(&g_hist[c * 256 + b], s);
    }
}

// ---------------------------------------------------------------------------
// K2b: compact candidates >= threshold bin, grid (SPLIT, NC)
// ---------------------------------------------------------------------------
__global__ __launch_bounds__(512, 1) void compact_kernel() {
    const int c = blockIdx.y, part = blockIdx.x;
    const int tid = threadIdx.x, lane = tid & 31;
    __shared__ int sB;
    if (tid == 0) {
        int cum = 0, b = 255;
        for (; b >= 0; --b) { cum += (int)g_hist[c * 256 + b]; if (cum >= KK) break; }
        sB = b < 0 ? 0 : b;
    }
    __syncthreads();
    const int B = sB;
    const int n4 = AN / 4 / SPLIT;
    const float4* row4 = reinterpret_cast<const float4*>(g_scoresT + (size_t)c * AN) + part * n4;
    const unsigned lt = (1u << lane) - 1u;
    const int iters = (n4 + 511) / 512;
    for (int k = 0; k < iters; ++k) {
        int i = tid + k * 512;
        bool act = (i < n4);
        float4 v = act ? row4[i] : make_float4(-1.f, -1.f, -1.f, -1.f);
        int base = (part * n4 + i) * 4;
#define BIN(x) ({ int b = (int)((x) * 256.0f); b = b < 0 ? 0 : (b > 255 ? 255 : b); b; })
        bool p0 = act && (BIN(v.x) >= B);
        bool p1 = act && (BIN(v.y) >= B);
        bool p2 = act && (BIN(v.z) >= B);
        bool p3 = act && (BIN(v.w) >= B);
#undef BIN
        unsigned m0 = __ballot_sync(0xFFFFFFFFu, p0);
        unsigned m1 = __ballot_sync(0xFFFFFFFFu, p1);
        unsigned m2 = __ballot_sync(0xFFFFFFFFu, p2);
        unsigned m3 = __ballot_sync(0xFFFFFFFFu, p3);
        int n0 = __popc(m0), n1 = __popc(m1), n2 = __popc(m2), n3 = __popc(m3);
        int tot = n0 + n1 + n2 + n3;
        int bp = 0;
        if (lane == 0 && tot) bp = atomicAdd(&g_cnt[c], tot);
        bp = __shfl_sync(0xFFFFFFFFu, bp, 0);
#define EMIT(pred, m, off, comp, idxoff)                                     \
        if (pred) {                                                          \
            int p = bp + (off) + __popc((m) & lt);                           \
            if (p < CAP)                                                     \
                g_cand[c * CAP + p] =                                        \
                    ((unsigned long long)(~order_key(comp)) << 32)           \
                    | (unsigned)(base + (idxoff));                           \
        }
        EMIT(p0, m0, 0,            v.x, 0)
        EMIT(p1, m1, n0,           v.y, 1)
        EMIT(p2, m2, n0 + n1,      v.z, 2)
        EMIT(p3, m3, n0 + n1 + n2, v.w, 3)
#undef EMIT
    }
}

// ---------------------------------------------------------------------------
// K2c: hybrid bitonic sort 2048 + decode, grid NC
// ---------------------------------------------------------------------------
__device__ __forceinline__ unsigned long long bx_exch(
        unsigned long long e, int j, bool asc, int lane) {
    unsigned long long p = __shfl_xor_sync(0xFFFFFFFFu, e, j);
    bool low = ((lane & j) == 0);
    bool keepmin = (low == asc);
    unsigned long long mn = (e < p) ? e : p;
    unsigned long long mx = (e < p) ? p : e;
    return keepmin ? mn : mx;
}

__global__ __launch_bounds__(1024, 1)
void sortdec_kernel(const float* __restrict__ reg, const float* __restrict__ anc) {
    __shared__ unsigned long long sb[CAP];
    const int c = blockIdx.x;
    const int tid = threadIdx.x, lane = tid & 31, wid = tid >> 5;

    int cnt = g_cnt[c]; if (cnt > CAP) cnt = CAP;
    sb[tid]        = (tid < cnt)        ? g_cand[c * CAP + tid]        : ~0ull;
    sb[tid + 1024] = (tid + 1024 < cnt) ? g_cand[c * CAP + tid + 1024] : ~0ull;
    __syncthreads();

    unsigned long long e0 = sb[64 * wid + lane];
    unsigned long long e1 = sb[64 * wid + 32 + lane];
#pragma unroll
    for (int k2 = 2; k2 <= 16; k2 <<= 1) {
#pragma unroll
        for (int j = k2 >> 1; j >= 1; j >>= 1) {
            bool a0 = ((lane & k2) == 0);
            e0 = bx_exch(e0, j, a0, lane);
            e1 = bx_exch(e1, j, a0, lane);
        }
    }
#pragma unroll
    for (int j = 16; j >= 1; j >>= 1) {
        e0 = bx_exch(e0, j, true, lane);
        e1 = bx_exch(e1, j, false, lane);
    }
    {
        bool A = ((wid & 1) == 0);
        unsigned long long mn = (e0 < e1) ? e0 : e1;
        unsigned long long mx = (e0 < e1) ? e1 : e0;
        e0 = A ? mn : mx; e1 = A ? mx : mn;
#pragma unroll
        for (int j = 16; j >= 1; j >>= 1) {
            e0 = bx_exch(e0, j, A, lane);
            e1 = bx_exch(e1, j, A, lane);
        }
    }
    for (int k2 = 128; k2 <= CAP; k2 <<= 1) {
        sb[64 * wid + lane] = e0;
        sb[64 * wid + 32 + lane] = e1;
        __syncthreads();
        for (int j = k2 >> 1; j >= 64; j >>= 1) {
            int i1 = ((tid & ~(j - 1)) << 1) | (tid & (j - 1));
            int i2 = i1 | j;
            unsigned long long a = sb[i1];
            unsigned long long b = sb[i2];
            bool asc = ((i1 & k2) == 0);
            if ((a > b) == asc) { sb[i1] = b; sb[i2] = a; }
            __syncthreads();
        }
        e0 = sb[64 * wid + lane];
        e1 = sb[64 * wid + 32 + lane];
        bool A = (((wid * 64) & k2) == 0);
        unsigned long long mn = (e0 < e1) ? e0 : e1;
        unsigned long long mx = (e0 < e1) ? e1 : e0;
        e0 = A ? mn : mx; e1 = A ? mx : mn;
#pragma unroll
        for (int j = 16; j >= 1; j >>= 1) {
            e0 = bx_exch(e0, j, A, lane);
            e1 = bx_exch(e1, j, A, lane);
        }
    }
    sb[64 * wid + lane] = e0;
    sb[64 * wid + 32 + lane] = e1;
    __syncthreads();

    float sc = 0.0f;
    if (tid < KK) {
        unsigned long long kv = sb[tid];
        if (kv != ~0ull) {
            unsigned kk = ~(unsigned)(kv >> 32);
            unsigned u = (kk & 0x80000000u) ? (kk ^ 0x80000000u) : ~kk;
            sc = __uint_as_float(u);
            int idx = (int)(kv & 0xFFFFFFFFull);
            float4 a = reinterpret_cast<const float4*>(anc)[idx];
            float4 r = reinterpret_cast<const float4*>(reg)[idx];
            float wa = a.z - a.x, ha = a.w - a.y;
            float cxa = a.x + 0.5f * wa, cya = a.y + 0.5f * ha;
            float cx = cxa + (r.x * 0.1f) * wa;
            float cy = cya + (r.y * 0.1f) * ha;
            float w = __expf(r.z * 0.2f) * wa;
            float h = __expf(r.w * 0.2f) * ha;
            float4 b;
            b.x = fminf(fmaxf(cx - 0.5f * w, 0.0f), 1024.0f);
            b.y = fminf(fmaxf(cy - 0.5f * h, 0.0f), 1024.0f);
            b.z = fminf(fmaxf(cx + 0.5f * w, 0.0f), 1024.0f);
            b.w = fminf(fmaxf(cy + 0.5f * h, 0.0f), 1024.0f);
            g_box[c * 1024 + tid] = b;
            g_score[c * 1024 + tid] = sc;
        } else {
            g_box[c * 1024 + tid] = make_float4(0.f, 0.f, 0.f, 0.f);
            g_score[c * 1024 + tid] = 0.0f;
        }
    } else {
        g_box[c * 1024 + tid] = make_float4(0.f, 0.f, 0.f, 0.f);
        g_score[c * 1024 + tid] = 0.0f;
    }
    unsigned bal = __ballot_sync(0xFFFFFFFFu, (tid < KK) && (sc > 0.05f));
    if (lane == 0) g_vb[c * 32 + wid] = bal;
}

// ---------------------------------------------------------------------------
// K3: NMS bitmask build, scalar FMNMX IoU, coalesced transposed stores
// bits for row i = bi*32+lane over j in block bj (IoU symmetric)
// ---------------------------------------------------------------------------
__global__ __launch_bounds__(256, 1) void mask_kernel() {
    __shared__ float4 sbox[1024];
    __shared__ float  sar[1024];
    const int c = blockIdx.y, p = blockIdx.x;
    const int tid = threadIdx.x, lane = tid & 31, wid = tid >> 5;

    for (int i = tid; i < 1024; i += 256) {
        float4 b = g_box[c * 1024 + i];
        sbox[i] = b;
        sar[i] = (b.z - b.x) * (b.w - b.y);
    }
    __syncthreads();

    int gw = p * 8 + wid;          // 0..87 ; 88 * 6 = 528 tasks
    int t0 = gw * 6;
    int bi = 0, rem = t0;
    while (rem >= 32 - bi) { rem -= 32 - bi; ++bi; }
    int bj = bi + rem;

    for (int s = 0; s < 6; ++s) {
        float4 br = sbox[bi * 32 + lane];       // row box (suppressor i)
        float arE = sar[bi * 32 + lane] + 1e-8f;
        unsigned bits = 0;
#pragma unroll
        for (int jj = 0; jj < 32; ++jj) {
            float4 bc = sbox[bj * 32 + jj];     // broadcast
            float ac = sar[bj * 32 + jj];
            float w = fminf(br.z, bc.z) - fmaxf(br.x, bc.x);
            float h = fminf(br.w, bc.w) - fmaxf(br.y, bc.y);
            float inter = fmaxf(w, 0.0f) * fmaxf(h, 0.0f);
            bool pr = (inter * 3.0f > arE + ac);   // iou > 0.5
            bits |= pr ? (1u << jj) : 0u;
        }
        if (bi == bj) {
            bits &= (0xFFFFFFFEu << lane);         // only jj > lane
            g_diag[c * 1024 + bi * 32 + lane] = bits;
        }
        g_maskT[(c * 32 + bj) * 1024 + bi * 32 + lane] = bits;  // coalesced
        if (++bj == 32) { ++bi; bj = bi; }
    }
}

// ---------------------------------------------------------------------------
// K4: serial greedy reduce + outputs, grid NC
// ---------------------------------------------------------------------------
__global__ __launch_bounds__(1024, 1) void reduce_kernel(float* __restrict__ out) {
    extern __shared__ unsigned smT[];     // [32 wordcols][1025 rows-padded]
    __shared__ unsigned s_diag[1024];
    __shared__ unsigned s_vb[32];
    __shared__ unsigned s_rm[32];
    const int c = blockIdx.x, tid = threadIdx.x, lane = tid & 31, wid = tid >> 5;

    const uint4* gm4 = reinterpret_cast<const uint4*>(g_maskT + c * 32768);
    int wq = tid & 3;
    int r4 = tid >> 2;            // 0..255 (4 rows each)
    int rb = r4 >> 3;             // row-block of these rows
#pragma unroll
    for (int k = 0; k < 8; ++k) {
        int wcol = k * 4 + wq;
        uint4 v = gm4[wcol * 256 + r4];
        if (wcol < rb) v = make_uint4(0u, 0u, 0u, 0u);   // lower triangle unused
        unsigned* d = &smT[wcol * 1025 + r4 * 4];
        d[0] = v.x; d[1] = v.y; d[2] = v.z; d[3] = v.w;
    }
    s_diag[tid] = g_diag[c * 1024 + tid];
    if (tid < 32) s_vb[tid] = g_vb[c * 32 + tid];
    __syncthreads();

    if (wid == 0) {
        unsigned removed = 0;              // lane owns word-col `lane`
        unsigned vbl = s_vb[lane];
        for (int b = 0; b < 32; ++b) {
            unsigned rmw = __shfl_sync(0xFFFFFFFFu, removed, b);
            unsigned vbw = __shfl_sync(0xFFFFFFFFu, vbl, b);
#pragma unroll
            for (int r = 0; r < 32; ++r) {
                unsigned dgr = s_diag[b * 32 + r];                 // broadcast
                unsigned mrr = smT[lane * 1025 + b * 32 + r];      // conflict-free
                bool kept = ((vbw >> r) & 1u) && !((rmw >> r) & 1u);
                if (kept) { rmw |= dgr; removed |= mrr; }
            }
        }
        s_rm[lane] = removed;
    }
    __syncthreads();

    if (tid < KK) {
        int o = c * KK + tid;
        unsigned rw = s_rm[tid >> 5];
        unsigned vb = s_vb[tid >> 5];
        bool kp = ((vb >> (tid & 31)) & 1u) && !((rw >> (tid & 31)) & 1u);
        float sc = g_score[c * 1024 + tid];
        float4 bb = g_box[c * 1024 + tid];
        out[o] = kp ? sc : 0.0f;
        out[NC * KK + o] = kp ? (float)c : -1.0f;
        reinterpret_cast<float4*>(out + 2 * NC * KK)[o] =
            kp ? bb : make_float4(0.f, 0.f, 0.f, 0.f);
        out[6 * NC * KK + o] = kp ? 1.0f : 0.0f;
    }
}

// ---------------------------------------------------------------------------
extern "C" void kernel_launch(void* const* d_in, const int* in_sizes, int n_in,
                              void* d_out, int out_size) {
    const float* cls = (const float*)d_in[0];
    const float* reg = (const float*)d_in[1];
    const float* anc = (const float*)d_in[2];
    float* out = (float*)d_out;

    transpose_kernel<<<dim3(AN / 64, 3), 512>>>(cls);

    int histSmem = 512 * 256;
    cudaFuncSetAttribute(hist_kernel,
                         cudaFuncAttributeMaxDynamicSharedMemorySize, histSmem);
    hist_kernel<<<dim3(SPLIT, NC), 512, histSmem>>>();

    compact_kernel<<<dim3(SPLIT, NC), 512>>>();

    sortdec_kernel<<<NC, 1024>>>(reg, anc);

    mask_kernel<<<dim3(PARTS, NC), 256>>>();

    int redSmem = 32 * 1025 * 4;
    cudaFuncSetAttribute(reduce_kernel,
                         cudaFuncAttributeMaxDynamicSharedMemorySize, redSmem);
    reduce_kernel<<<NC, 1024, redSmem>>>(out);
}

// round 6
// speedup vs baseline: 1.1415x; 1.1415x over previous
#include <cuda_runtime.h>
#include <stdint.h>

#define AN 196416
#define N4 (AN / 4)
#define NC 80
#define KK 1000
#define CAP 2048
#define PARTS 11   // mask CTAs per class: 11*8 warps = 88, x6 tasks = 528

// ---------------- global scratch ----------------
__device__ float    g_scoresT[(size_t)NC * AN];
__device__ float4   g_box  [NC * 1024];
__device__ float    g_score[NC * 1024];
__device__ unsigned g_vb   [NC * 32];
__device__ unsigned g_maskT[NC * 32 * 1024];   // [class][wordcol][row]
__device__ unsigned g_diag [NC * 1024];

__device__ __forceinline__ unsigned order_key(float x) {
    unsigned u = __float_as_uint(x);
    return (u & 0x80000000u) ? ~u : (u | 0x80000000u);
}

// ---------------------------------------------------------------------------
// K1: transpose [AN, NC] -> [NC, AN]
// ---------------------------------------------------------------------------
__global__ __launch_bounds__(512) void transpose_kernel(const float* __restrict__ cls) {
    __shared__ float tile[2][32][33];
    int tid = threadIdx.x;
    int c0 = blockIdx.y * 32;
    int a0 = blockIdx.x * 64;
    int t = tid >> 8;                 // which 32-anchor tile
    int r = (tid >> 3) & 31;          // anchor row in tile
    int q = tid & 7;                  // class quad
    int c = c0 + q * 4;
    float4 v = make_float4(0.f, 0.f, 0.f, 0.f);
    if (c < NC)
        v = *reinterpret_cast<const float4*>(&cls[(size_t)(a0 + t * 32 + r) * NC + c]);
    tile[t][r][q * 4 + 0] = v.x;
    tile[t][r][q * 4 + 1] = v.y;
    tile[t][r][q * 4 + 2] = v.z;
    tile[t][r][q * 4 + 3] = v.w;
    __syncthreads();
    int cc = (tid & 255) >> 3;        // class within tile
    int ct = c0 + cc;
    if (ct < NC) {
        float4 o;
        o.x = tile[t][q * 4 + 0][cc];
        o.y = tile[t][q * 4 + 1][cc];
        o.z = tile[t][q * 4 + 2][cc];
        o.w = tile[t][q * 4 + 3][cc];
        *reinterpret_cast<float4*>(&g_scoresT[(size_t)ct * AN + a0 + t * 32 + q * 4]) = o;
    }
}

// ---------------------------------------------------------------------------
// K2: fused per-class hist -> threshold -> compact -> sort -> decode, grid NC
// ---------------------------------------------------------------------------
__device__ __forceinline__ unsigned long long bx_exch(
        unsigned long long e, int j, bool asc, int lane) {
    unsigned long long p = __shfl_xor_sync(0xFFFFFFFFu, e, j);
    bool low = ((lane & j) == 0);
    bool keepmin = (low == asc);
    unsigned long long mn = (e < p) ? e : p;
    unsigned long long mx = (e < p) ? p : e;
    return keepmin ? mn : mx;
}

__global__ __launch_bounds__(1024, 1)
void selsort_kernel(const float* __restrict__ reg, const float* __restrict__ anc) {
    extern __shared__ char dsm[];
    unsigned char* h8 = reinterpret_cast<unsigned char*>(dsm);          // 128KB
    unsigned long long* sb = reinterpret_cast<unsigned long long*>(dsm); // alias (16KB, after hist dead)
    __shared__ unsigned s_tot[256];
    __shared__ int sB, s_cnt;

    const int c = blockIdx.x;
    const int tid = threadIdx.x, lane = tid & 31, wid = tid >> 5;
    const float4* __restrict__ row4 =
        reinterpret_cast<const float4*>(g_scoresT + (size_t)c * AN);

    // ---- zero hist ----
    unsigned* h32 = reinterpret_cast<unsigned*>(h8);
    for (int i = tid; i < 512 * 256 / 4; i += 1024) h32[i] = 0;
    __syncthreads();

    // ---- one-pass per-thread u8 histogram (512 threads own slots) ----
    if (tid < 512) {
        const int slot = (tid & 127) * 4 + (tid >> 7);   // conflict-free byte slot
        for (int i = tid; i < N4; i += 512) {
            float4 v = row4[i];
#define HB(x) { int b = (int)((x) * 256.0f); b = b < 0 ? 0 : (b > 255 ? 255 : b); \
                h8[b * 512 + slot] += 1; }
            HB(v.x) HB(v.y) HB(v.z) HB(v.w)
#undef HB
        }
    }
    __syncthreads();

    // ---- per-bin totals (thread t sums bin t; rotated to avoid conflicts) ----
    if (tid < 256) {
        const unsigned* p = reinterpret_cast<const unsigned*>(h8) + tid * 128;
        unsigned s = 0;
#pragma unroll 16
        for (int w = 0; w < 128; ++w)
            s = __dp4a(p[(w + tid) & 127], 0x01010101u, s);
        s_tot[tid] = s;
    }
    __syncthreads();

    if (tid == 0) {
        int cum = 0, b = 255;
        for (; b >= 0; --b) { cum += (int)s_tot[b]; if (cum >= KK) break; }
        sB = b < 0 ? 0 : b;
        s_cnt = 0;
    }
    __syncthreads();
    const int B = sB;

    // ---- compact into smem candidate buffer (h8 dead; sb aliases it) ----
    const unsigned lt = (1u << lane) - 1u;
    for (int k = 0; k < (N4 + 1023) / 1024; ++k) {
        int i = tid + k * 1024;
        bool act = (i < N4);
        float4 v = act ? row4[i] : make_float4(-1.f, -1.f, -1.f, -1.f);
        int base = i * 4;
#define BIN(x) ({ int b = (int)((x) * 256.0f); b = b < 0 ? 0 : (b > 255 ? 255 : b); b; })
        bool p0 = act && (BIN(v.x) >= B);
        bool p1 = act && (BIN(v.y) >= B);
        bool p2 = act && (BIN(v.z) >= B);
        bool p3 = act && (BIN(v.w) >= B);
#undef BIN
        unsigned m0 = __ballot_sync(0xFFFFFFFFu, p0);
        unsigned m1 = __ballot_sync(0xFFFFFFFFu, p1);
        unsigned m2 = __ballot_sync(0xFFFFFFFFu, p2);
        unsigned m3 = __ballot_sync(0xFFFFFFFFu, p3);
        int n0 = __popc(m0), n1 = __popc(m1), n2 = __popc(m2), n3 = __popc(m3);
        int tot = n0 + n1 + n2 + n3;
        int bp = 0;
        if (lane == 0 && tot) bp = atomicAdd(&s_cnt, tot);
        bp = __shfl_sync(0xFFFFFFFFu, bp, 0);
#define EMIT(pred, m, off, comp, idxoff)                                     \
        if (pred) {                                                          \
            int p = bp + (off) + __popc((m) & lt);                           \
            if (p < CAP)                                                     \
                sb[p] = ((unsigned long long)(~order_key(comp)) << 32)       \
                        | (unsigned)(base + (idxoff));                       \
        }
        EMIT(p0, m0, 0,            v.x, 0)
        EMIT(p1, m1, n0,           v.y, 1)
        EMIT(p2, m2, n0 + n1,      v.z, 2)
        EMIT(p3, m3, n0 + n1 + n2, v.w, 3)
#undef EMIT
    }
    __syncthreads();
    {
        int cnt = s_cnt; if (cnt > CAP) cnt = CAP;
        for (int i = cnt + tid; i < CAP; i += 1024) sb[i] = ~0ull;
    }
    __syncthreads();

    // ---- hybrid bitonic sort 2048 (asc u64 = score desc, idx asc) ----
    unsigned long long e0 = sb[64 * wid + lane];
    unsigned long long e1 = sb[64 * wid + 32 + lane];
#pragma unroll
    for (int k2 = 2; k2 <= 16; k2 <<= 1) {
#pragma unroll
        for (int j = k2 >> 1; j >= 1; j >>= 1) {
            bool a0 = ((lane & k2) == 0);
            e0 = bx_exch(e0, j, a0, lane);
            e1 = bx_exch(e1, j, a0, lane);
        }
    }
#pragma unroll
    for (int j = 16; j >= 1; j >>= 1) {
        e0 = bx_exch(e0, j, true, lane);
        e1 = bx_exch(e1, j, false, lane);
    }
    {
        bool A = ((wid & 1) == 0);
        unsigned long long mn = (e0 < e1) ? e0 : e1;
        unsigned long long mx = (e0 < e1) ? e1 : e0;
        e0 = A ? mn : mx; e1 = A ? mx : mn;
#pragma unroll
        for (int j = 16; j >= 1; j >>= 1) {
            e0 = bx_exch(e0, j, A, lane);
            e1 = bx_exch(e1, j, A, lane);
        }
    }
    for (int k2 = 128; k2 <= CAP; k2 <<= 1) {
        sb[64 * wid + lane] = e0;
        sb[64 * wid + 32 + lane] = e1;
        __syncthreads();
        for (int j = k2 >> 1; j >= 64; j >>= 1) {
            int i1 = ((tid & ~(j - 1)) << 1) | (tid & (j - 1));
            int i2 = i1 | j;
            unsigned long long a = sb[i1];
            unsigned long long b = sb[i2];
            bool asc = ((i1 & k2) == 0);
            if ((a > b) == asc) { sb[i1] = b; sb[i2] = a; }
            __syncthreads();
        }
        e0 = sb[64 * wid + lane];
        e1 = sb[64 * wid + 32 + lane];
        bool A = (((wid * 64) & k2) == 0);
        unsigned long long mn = (e0 < e1) ? e0 : e1;
        unsigned long long mx = (e0 < e1) ? e1 : e0;
        e0 = A ? mn : mx; e1 = A ? mx : mn;
#pragma unroll
        for (int j = 16; j >= 1; j >>= 1) {
            e0 = bx_exch(e0, j, A, lane);
            e1 = bx_exch(e1, j, A, lane);
        }
    }
    sb[64 * wid + lane] = e0;
    sb[64 * wid + 32 + lane] = e1;
    __syncthreads();

    // ---- decode + clip -> global scratch ----
    float sc = 0.0f;
    if (tid < KK) {
        unsigned long long kv = sb[tid];
        if (kv != ~0ull) {
            unsigned kk = ~(unsigned)(kv >> 32);
            unsigned u = (kk & 0x80000000u) ? (kk ^ 0x80000000u) : ~kk;
            sc = __uint_as_float(u);
            int idx = (int)(kv & 0xFFFFFFFFull);
            float4 a = reinterpret_cast<const float4*>(anc)[idx];
            float4 r = reinterpret_cast<const float4*>(reg)[idx];
            float wa = a.z - a.x, ha = a.w - a.y;
            float cxa = a.x + 0.5f * wa, cya = a.y + 0.5f * ha;
            float cx = cxa + (r.x * 0.1f) * wa;
            float cy = cya + (r.y * 0.1f) * ha;
            float w = __expf(r.z * 0.2f) * wa;
            float h = __expf(r.w * 0.2f) * ha;
            float4 b;
            b.x = fminf(fmaxf(cx - 0.5f * w, 0.0f), 1024.0f);
            b.y = fminf(fmaxf(cy - 0.5f * h, 0.0f), 1024.0f);
            b.z = fminf(fmaxf(cx + 0.5f * w, 0.0f), 1024.0f);
            b.w = fminf(fmaxf(cy + 0.5f * h, 0.0f), 1024.0f);
            g_box[c * 1024 + tid] = b;
            g_score[c * 1024 + tid] = sc;
        } else {
            g_box[c * 1024 + tid] = make_float4(0.f, 0.f, 0.f, 0.f);
            g_score[c * 1024 + tid] = 0.0f;
        }
    } else {
        g_box[c * 1024 + tid] = make_float4(0.f, 0.f, 0.f, 0.f);
        g_score[c * 1024 + tid] = 0.0f;
    }
    unsigned bal = __ballot_sync(0xFFFFFFFFu, (tid < KK) && (sc > 0.05f));
    if (lane == 0) g_vb[c * 32 + wid] = bal;
}

// ---------------------------------------------------------------------------
// K3: NMS bitmask build, coalesced transposed stores
// ---------------------------------------------------------------------------
__global__ __launch_bounds__(256, 1) void mask_kernel() {
    __shared__ float4 sbox[1024];
    __shared__ float  sar[1024];
    const int c = blockIdx.y, p = blockIdx.x;
    const int tid = threadIdx.x, lane = tid & 31, wid = tid >> 5;

    for (int i = tid; i < 1024; i += 256) {
        float4 b = g_box[c * 1024 + i];
        sbox[i] = b;
        sar[i] = (b.z - b.x) * (b.w - b.y);
    }
    __syncthreads();

    int gw = p * 8 + wid;          // 0..87 ; 88 * 6 = 528 tasks
    int t0 = gw * 6;
    int bi = 0, rem = t0;
    while (rem >= 32 - bi) { rem -= 32 - bi; ++bi; }
    int bj = bi + rem;

    for (int s = 0; s < 6; ++s) {
        float4 br = sbox[bi * 32 + lane];       // row box (suppressor i)
        float arE = sar[bi * 32 + lane] + 1e-8f;
        unsigned bits = 0;
#pragma unroll
        for (int jj = 0; jj < 32; ++jj) {
            float4 bc = sbox[bj * 32 + jj];     // broadcast
            float ac = sar[bj * 32 + jj];
            float w = fminf(br.z, bc.z) - fmaxf(br.x, bc.x);
            float h = fminf(br.w, bc.w) - fmaxf(br.y, bc.y);
            float inter = fmaxf(w, 0.0f) * fmaxf(h, 0.0f);
            bool pr = (inter * 3.0f > arE + ac);   // iou > 0.5
            bits |= pr ? (1u << jj) : 0u;
        }
        if (bi == bj) {
            bits &= (0xFFFFFFFEu << lane);         // only jj > lane
            g_diag[c * 1024 + bi * 32 + lane] = bits;
        }
        g_maskT[(c * 32 + bj) * 1024 + bi * 32 + lane] = bits;  // coalesced
        if (++bj == 32) { ++bi; bj = bi; }
    }
}

// ---------------------------------------------------------------------------
// K4: serial greedy reduce + outputs, grid NC
// ---------------------------------------------------------------------------
__global__ __launch_bounds__(1024, 1) void reduce_kernel(float* __restrict__ out) {
    extern __shared__ unsigned smT[];     // [32 wordcols][1025 rows-padded]
    __shared__ unsigned s_diag[1024];
    __shared__ unsigned s_vb[32];
    __shared__ unsigned s_rm[32];
    const int c = blockIdx.x, tid = threadIdx.x, lane = tid & 31, wid = tid >> 5;

    const uint4* gm4 = reinterpret_cast<const uint4*>(g_maskT + c * 32768);
    int wq = tid & 3;
    int r4 = tid >> 2;            // 0..255 (4 rows each)
    int rb = r4 >> 3;             // row-block of these rows
#pragma unroll
    for (int k = 0; k < 8; ++k) {
        int wcol = k * 4 + wq;
        uint4 v = gm4[wcol * 256 + r4];
        if (wcol < rb) v = make_uint4(0u, 0u, 0u, 0u);   // lower triangle unused
        unsigned* d = &smT[wcol * 1025 + r4 * 4];
        d[0] = v.x; d[1] = v.y; d[2] = v.z; d[3] = v.w;
    }
    s_diag[tid] = g_diag[c * 1024 + tid];
    if (tid < 32) s_vb[tid] = g_vb[c * 32 + tid];
    __syncthreads();

    if (wid == 0) {
        unsigned removed = 0;              // lane owns word-col `lane`
        unsigned vbl = s_vb[lane];
        for (int b = 0; b < 32; ++b) {
            unsigned rmw = __shfl_sync(0xFFFFFFFFu, removed, b);
            unsigned vbw = __shfl_sync(0xFFFFFFFFu, vbl, b);
#pragma unroll
            for (int r = 0; r < 32; ++r) {
                unsigned dgr = s_diag[b * 32 + r];                 // broadcast
                unsigned mrr = smT[lane * 1025 + b * 32 + r];      // conflict-free
                bool kept = ((vbw >> r) & 1u) && !((rmw >> r) & 1u);
                if (kept) { rmw |= dgr; removed |= mrr; }
            }
        }
        s_rm[lane] = removed;
    }
    __syncthreads();

    if (tid < KK) {
        int o = c * KK + tid;
        unsigned rw = s_rm[tid >> 5];
        unsigned vb = s_vb[tid >> 5];
        bool kp = ((vb >> (tid & 31)) & 1u) && !((rw >> (tid & 31)) & 1u);
        float sc = g_score[c * 1024 + tid];
        float4 bb = g_box[c * 1024 + tid];
        out[o] = kp ? sc : 0.0f;
        out[NC * KK + o] = kp ? (float)c : -1.0f;
        reinterpret_cast<float4*>(out + 2 * NC * KK)[o] =
            kp ? bb : make_float4(0.f, 0.f, 0.f, 0.f);
        out[6 * NC * KK + o] = kp ? 1.0f : 0.0f;
    }
}

// ---------------------------------------------------------------------------
extern "C" void kernel_launch(void* const* d_in, const int* in_sizes, int n_in,
                              void* d_out, int out_size) {
    const float* cls = (const float*)d_in[0];
    const float* reg = (const float*)d_in[1];
    const float* anc = (const float*)d_in[2];
    float* out = (float*)d_out;

    transpose_kernel<<<dim3(AN / 64, 3), 512>>>(cls);

    int selSmem = 512 * 256;   // 128KB (sb aliases the first 16KB)
    cudaFuncSetAttribute(selsort_kernel,
                         cudaFuncAttributeMaxDynamicSharedMemorySize, selSmem);
    selsort_kernel<<<NC, 1024, selSmem>>>(reg, anc);

    mask_kernel<<<dim3(PARTS, NC), 256>>>();

    int redSmem = 32 * 1025 * 4;
    cudaFuncSetAttribute(reduce_kernel,
                         cudaFuncAttributeMaxDynamicSharedMemorySize, redSmem);
    reduce_kernel<<<NC, 1024, redSmem>>>(out);
}

// round 7
// speedup vs baseline: 1.3060x; 1.1441x over previous
#include <cuda_runtime.h>
#include <stdint.h>

#define AN 196416
#define NC 80
#define KK 1000
#define CAP 2048
#define PARTS 11
#define TOT4 (AN * NC / 4)          // 3,928,320 float4s
#define COLGRID 1184
#define T0 (254.0f / 256.0f)

// ---------------- global scratch ----------------
__device__ int                g_cnt[NC];
__device__ unsigned long long g_cand[NC * CAP];
__device__ float4             g_box  [NC * 1024];
__device__ float              g_score[NC * 1024];
__device__ unsigned           g_vb   [NC * 32];
__device__ unsigned           g_maskT[NC * 32 * 1024];   // [class][wordcol][row]
__device__ unsigned           g_diag [NC * 1024];

__device__ __forceinline__ unsigned order_key(float x) {
    unsigned u = __float_as_uint(x);
    return (u & 0x80000000u) ? ~u : (u | 0x80000000u);
}

// ---------------------------------------------------------------------------
// K0: zero per-class counters (graph replays need re-init)
// ---------------------------------------------------------------------------
__global__ void init_kernel() {
    if (threadIdx.x < NC) g_cnt[threadIdx.x] = 0;
}

// ---------------------------------------------------------------------------
// K1: chip-wide candidate collect from ORIGINAL [AN, NC] layout.
// A float4 never crosses an anchor row (NC=80 ≡ 0 mod 4).
// ---------------------------------------------------------------------------
__global__ __launch_bounds__(256) void collect_kernel(const float* __restrict__ cls) {
    const float4* __restrict__ p4 = reinterpret_cast<const float4*>(cls);
    for (int i = blockIdx.x * 256 + threadIdx.x; i < TOT4; i += COLGRID * 256) {
        float4 v = p4[i];
        if (v.x >= T0 || v.y >= T0 || v.z >= T0 || v.w >= T0) {
            int f = i * 4;
            int a = f / NC;
            int c0 = f - a * NC;
#define PUSH(x, k)                                                            \
            if ((x) >= T0) {                                                  \
                int cc = c0 + (k);                                            \
                int pos = atomicAdd(&g_cnt[cc], 1);                           \
                if (pos < CAP)                                                \
                    g_cand[cc * CAP + pos] =                                  \
                        ((unsigned long long)(~order_key(x)) << 32)           \
                        | (unsigned)a;                                        \
            }
            PUSH(v.x, 0) PUSH(v.y, 1) PUSH(v.z, 2) PUSH(v.w, 3)
#undef PUSH
        }
    }
}

// ---------------------------------------------------------------------------
// K2: per-class sort + decode (fast path from g_cand; exact slow path rescue)
// ---------------------------------------------------------------------------
__device__ __forceinline__ unsigned long long bx_exch(
        unsigned long long e, int j, bool asc, int lane) {
    unsigned long long p = __shfl_xor_sync(0xFFFFFFFFu, e, j);
    bool low = ((lane & j) == 0);
    bool keepmin = (low == asc);
    unsigned long long mn = (e < p) ? e : p;
    unsigned long long mx = (e < p) ? p : e;
    return keepmin ? mn : mx;
}

__global__ __launch_bounds__(1024, 1)
void sortdec_kernel(const float* __restrict__ cls,
                    const float* __restrict__ reg,
                    const float* __restrict__ anc) {
    extern __shared__ char dsm[];                                  // 64KB
    unsigned* hist = reinterpret_cast<unsigned*>(dsm);             // 16x1024 u32
    unsigned long long* sb = reinterpret_cast<unsigned long long*>(dsm); // alias 16KB
    __shared__ unsigned s_totals[16];
    __shared__ float s_blo;
    __shared__ int s_above, s_cand, s_cnt;

    const int c = blockIdx.x;
    const int tid = threadIdx.x, lane = tid & 31, wid = tid >> 5;

    int cnt = g_cnt[c];
    bool fast = (cnt >= KK && cnt <= CAP);

    if (fast) {
        sb[tid]        = (tid < cnt)        ? g_cand[c * CAP + tid]        : ~0ull;
        sb[tid + 1024] = (tid + 1024 < cnt) ? g_cand[c * CAP + tid + 1024] : ~0ull;
        __syncthreads();
    } else {
        // ---- exact slow path: 16-way hierarchical refine on strided column
        float blo = 0.0f, bwid = 1.0f / 16.0f;
        int aboveCnt = 0, candTotal = AN;
        for (int level = 0; level < 4; ++level) {
#pragma unroll
            for (int b = 0; b < 16; ++b) hist[b * 1024 + tid] = 0;
            __syncthreads();
            const float inv = 1.0f / bwid;
            for (int a = tid; a < AN; a += 1024) {
                float x = cls[(size_t)a * NC + c];
                if (level == 0) {
                    int b = (int)(x * 16.0f);
                    b = b < 0 ? 0 : (b > 15 ? 15 : b);
                    hist[b * 1024 + tid] += 1u;
                } else {
                    float t = (x - blo) * inv;
                    if (x >= blo && t < 16.0f)
                        hist[(int)t * 1024 + tid] += 1u;
                }
            }
            __syncthreads();
            if (wid < 16) {
                unsigned s = 0;
#pragma unroll
                for (int k = 0; k < 32; ++k) s += hist[wid * 1024 + k * 32 + lane];
#pragma unroll
                for (int o = 16; o > 0; o >>= 1) s += __shfl_down_sync(0xFFFFFFFFu, s, o);
                if (lane == 0) s_totals[wid] = s;
            }
            __syncthreads();
            if (tid == 0) {
                int cum = aboveCnt, b = 15;
                for (; b >= 0; --b) { cum += (int)s_totals[b]; if (cum >= KK) break; }
                if (b < 0) b = 0;
                s_blo = blo + (float)b * bwid;
                s_above = cum - (int)s_totals[b];
                s_cand = cum;
            }
            __syncthreads();
            blo = s_blo; aboveCnt = s_above; candTotal = s_cand;
            bwid *= (1.0f / 16.0f);
            __syncthreads();
            if (candTotal <= 1800) break;
        }
        const float thr = blo - bwid;
        if (tid == 0) s_cnt = 0;
        __syncthreads();
        for (int a = tid; a < AN; a += 1024) {
            float x = cls[(size_t)a * NC + c];
            if (x >= thr) {
                int p = atomicAdd(&s_cnt, 1);
                if (p < CAP)
                    sb[p] = ((unsigned long long)(~order_key(x)) << 32) | (unsigned)a;
            }
        }
        __syncthreads();
        int cn = s_cnt; if (cn > CAP) cn = CAP;
        for (int i = cn + tid; i < CAP; i += 1024) sb[i] = ~0ull;
        __syncthreads();
    }

    // ---- hybrid bitonic sort 2048 (asc u64 = score desc, idx asc) ----
    unsigned long long e0 = sb[64 * wid + lane];
    unsigned long long e1 = sb[64 * wid + 32 + lane];
#pragma unroll
    for (int k2 = 2; k2 <= 16; k2 <<= 1) {
#pragma unroll
        for (int j = k2 >> 1; j >= 1; j >>= 1) {
            bool a0 = ((lane & k2) == 0);
            e0 = bx_exch(e0, j, a0, lane);
            e1 = bx_exch(e1, j, a0, lane);
        }
    }
#pragma unroll
    for (int j = 16; j >= 1; j >>= 1) {
        e0 = bx_exch(e0, j, true, lane);
        e1 = bx_exch(e1, j, false, lane);
    }
    {
        bool A = ((wid & 1) == 0);
        unsigned long long mn = (e0 < e1) ? e0 : e1;
        unsigned long long mx = (e0 < e1) ? e1 : e0;
        e0 = A ? mn : mx; e1 = A ? mx : mn;
#pragma unroll
        for (int j = 16; j >= 1; j >>= 1) {
            e0 = bx_exch(e0, j, A, lane);
            e1 = bx_exch(e1, j, A, lane);
        }
    }
    for (int k2 = 128; k2 <= CAP; k2 <<= 1) {
        sb[64 * wid + lane] = e0;
        sb[64 * wid + 32 + lane] = e1;
        __syncthreads();
        for (int j = k2 >> 1; j >= 64; j >>= 1) {
            int i1 = ((tid & ~(j - 1)) << 1) | (tid & (j - 1));
            int i2 = i1 | j;
            unsigned long long a = sb[i1];
            unsigned long long b = sb[i2];
            bool asc = ((i1 & k2) == 0);
            if ((a > b) == asc) { sb[i1] = b; sb[i2] = a; }
            __syncthreads();
        }
        e0 = sb[64 * wid + lane];
        e1 = sb[64 * wid + 32 + lane];
        bool A = (((wid * 64) & k2) == 0);
        unsigned long long mn = (e0 < e1) ? e0 : e1;
        unsigned long long mx = (e0 < e1) ? e1 : e0;
        e0 = A ? mn : mx; e1 = A ? mx : mn;
#pragma unroll
        for (int j = 16; j >= 1; j >>= 1) {
            e0 = bx_exch(e0, j, A, lane);
            e1 = bx_exch(e1, j, A, lane);
        }
    }
    sb[64 * wid + lane] = e0;
    sb[64 * wid + 32 + lane] = e1;
    __syncthreads();

    // ---- decode + clip -> global scratch ----
    float sc = 0.0f;
    if (tid < KK) {
        unsigned long long kv = sb[tid];
        if (kv != ~0ull) {
            unsigned kk = ~(unsigned)(kv >> 32);
            unsigned u = (kk & 0x80000000u) ? (kk ^ 0x80000000u) : ~kk;
            sc = __uint_as_float(u);
            int idx = (int)(kv & 0xFFFFFFFFull);
            float4 a = reinterpret_cast<const float4*>(anc)[idx];
            float4 r = reinterpret_cast<const float4*>(reg)[idx];
            float wa = a.z - a.x, ha = a.w - a.y;
            float cxa = a.x + 0.5f * wa, cya = a.y + 0.5f * ha;
            float cx = cxa + (r.x * 0.1f) * wa;
            float cy = cya + (r.y * 0.1f) * ha;
            float w = __expf(r.z * 0.2f) * wa;
            float h = __expf(r.w * 0.2f) * ha;
            float4 b;
            b.x = fminf(fmaxf(cx - 0.5f * w, 0.0f), 1024.0f);
            b.y = fminf(fmaxf(cy - 0.5f * h, 0.0f), 1024.0f);
            b.z = fminf(fmaxf(cx + 0.5f * w, 0.0f), 1024.0f);
            b.w = fminf(fmaxf(cy + 0.5f * h, 0.0f), 1024.0f);
            g_box[c * 1024 + tid] = b;
            g_score[c * 1024 + tid] = sc;
        } else {
            g_box[c * 1024 + tid] = make_float4(0.f, 0.f, 0.f, 0.f);
            g_score[c * 1024 + tid] = 0.0f;
        }
    } else {
        g_box[c * 1024 + tid] = make_float4(0.f, 0.f, 0.f, 0.f);
        g_score[c * 1024 + tid] = 0.0f;
    }
    unsigned bal = __ballot_sync(0xFFFFFFFFu, (tid < KK) && (sc > 0.05f));
    if (lane == 0) g_vb[c * 32 + wid] = bal;
}

// ---------------------------------------------------------------------------
// K3: NMS bitmask build, coalesced transposed stores
// ---------------------------------------------------------------------------
__global__ __launch_bounds__(256, 1) void mask_kernel() {
    __shared__ float4 sbox[1024];
    __shared__ float  sar[1024];
    const int c = blockIdx.y, p = blockIdx.x;
    const int tid = threadIdx.x, lane = tid & 31, wid = tid >> 5;

    for (int i = tid; i < 1024; i += 256) {
        float4 b = g_box[c * 1024 + i];
        sbox[i] = b;
        sar[i] = (b.z - b.x) * (b.w - b.y);
    }
    __syncthreads();

    int gw = p * 8 + wid;          // 0..87 ; 88 * 6 = 528 tasks
    int t0 = gw * 6;
    int bi = 0, rem = t0;
    while (rem >= 32 - bi) { rem -= 32 - bi; ++bi; }
    int bj = bi + rem;

    for (int s = 0; s < 6; ++s) {
        float4 br = sbox[bi * 32 + lane];
        float arE = sar[bi * 32 + lane] + 1e-8f;
        unsigned bits = 0;
#pragma unroll
        for (int jj = 0; jj < 32; ++jj) {
            float4 bc = sbox[bj * 32 + jj];     // broadcast
            float ac = sar[bj * 32 + jj];
            float w = fminf(br.z, bc.z) - fmaxf(br.x, bc.x);
            float h = fminf(br.w, bc.w) - fmaxf(br.y, bc.y);
            float inter = fmaxf(w, 0.0f) * fmaxf(h, 0.0f);
            bool pr = (inter * 3.0f > arE + ac);   // iou > 0.5
            bits |= pr ? (1u << jj) : 0u;
        }
        if (bi == bj) {
            bits &= (0xFFFFFFFEu << lane);         // only jj > lane
            g_diag[c * 1024 + bi * 32 + lane] = bits;
        }
        g_maskT[(c * 32 + bj) * 1024 + bi * 32 + lane] = bits;  // coalesced
        if (++bj == 32) { ++bi; bj = bi; }
    }
}

// ---------------------------------------------------------------------------
// K4: serial greedy reduce + outputs, grid NC
// ---------------------------------------------------------------------------
__global__ __launch_bounds__(1024, 1) void reduce_kernel(float* __restrict__ out) {
    extern __shared__ unsigned smT[];     // [32 wordcols][1025 rows-padded]
    __shared__ unsigned s_diag[1024];
    __shared__ unsigned s_vb[32];
    __shared__ unsigned s_rm[32];
    const int c = blockIdx.x, tid = threadIdx.x, lane = tid & 31, wid = tid >> 5;

    const uint4* gm4 = reinterpret_cast<const uint4*>(g_maskT + c * 32768);
    int wq = tid & 3;
    int r4 = tid >> 2;
    int rb = r4 >> 3;
#pragma unroll
    for (int k = 0; k < 8; ++k) {
        int wcol = k * 4 + wq;
        uint4 v = gm4[wcol * 256 + r4];
        if (wcol < rb) v = make_uint4(0u, 0u, 0u, 0u);
        unsigned* d = &smT[wcol * 1025 + r4 * 4];
        d[0] = v.x; d[1] = v.y; d[2] = v.z; d[3] = v.w;
    }
    s_diag[tid] = g_diag[c * 1024 + tid];
    if (tid < 32) s_vb[tid] = g_vb[c * 32 + tid];
    __syncthreads();

    if (wid == 0) {
        unsigned removed = 0;
        unsigned vbl = s_vb[lane];
        for (int b = 0; b < 32; ++b) {
            unsigned rmw = __shfl_sync(0xFFFFFFFFu, removed, b);
            unsigned vbw = __shfl_sync(0xFFFFFFFFu, vbl, b);
#pragma unroll
            for (int r = 0; r < 32; ++r) {
                unsigned dgr = s_diag[b * 32 + r];
                unsigned mrr = smT[lane * 1025 + b * 32 + r];
                bool kept = ((vbw >> r) & 1u) && !((rmw >> r) & 1u);
                if (kept) { rmw |= dgr; removed |= mrr; }
            }
        }
        s_rm[lane] = removed;
    }
    __syncthreads();

    if (tid < KK) {
        int o = c * KK + tid;
        unsigned rw = s_rm[tid >> 5];
        unsigned vb = s_vb[tid >> 5];
        bool kp = ((vb >> (tid & 31)) & 1u) && !((rw >> (tid & 31)) & 1u);
        float sc = g_score[c * 1024 + tid];
        float4 bb = g_box[c * 1024 + tid];
        out[o] = kp ? sc : 0.0f;
        out[NC * KK + o] = kp ? (float)c : -1.0f;
        reinterpret_cast<float4*>(out + 2 * NC * KK)[o] =
            kp ? bb : make_float4(0.f, 0.f, 0.f, 0.f);
        out[6 * NC * KK + o] = kp ? 1.0f : 0.0f;
    }
}

// ---------------------------------------------------------------------------
extern "C" void kernel_launch(void* const* d_in, const int* in_sizes, int n_in,
                              void* d_out, int out_size) {
    const float* cls = (const float*)d_in[0];
    const float* reg = (const float*)d_in[1];
    const float* anc = (const float*)d_in[2];
    float* out = (float*)d_out;

    init_kernel<<<1, 128>>>();

    collect_kernel<<<COLGRID, 256>>>(cls);

    int selSmem = 16 * 1024 * 4;   // 64KB (sb aliases first 16KB)
    cudaFuncSetAttribute(sortdec_kernel,
                         cudaFuncAttributeMaxDynamicSharedMemorySize, selSmem);
    sortdec_kernel<<<NC, 1024, selSmem>>>(cls, reg, anc);

    mask_kernel<<<dim3(PARTS, NC), 256>>>();

    int redSmem = 32 * 1025 * 4;
    cudaFuncSetAttribute(reduce_kernel,
                         cudaFuncAttributeMaxDynamicSharedMemorySize, redSmem);
    reduce_kernel<<<NC, 1024, redSmem>>>(out);
}